// round 16
// baseline (speedup 1.0000x reference)
#include <cuda_runtime.h>
#include <cuda_fp16.h>
#include <mma.h>
#include <cstdint>

using namespace nvcuda;

#define NB 4
#define NL 1024
#define ND 256
#define NH 8
#define NHD 2048
#define NBL 4096
#define ATT ((size_t)NB * NH * NL * NL)

#define BKK 64
#define LDS_AB 72              // BK(64) + 8 pad -> 144B rows, LDSM conflict-free
#define PLE (128 * LDS_AB)     // elems per 128-row plane tile (9216)
#define PLB (PLE * 2)          // bytes per 128-row plane (18432)
#define LDC_S 132
#define STGW ((128 + 256) * LDS_AB * 2)   // wide stage bytes (55296)
#define SMEM_11 (2 * 2 * PLB)             // narrow: 73728 (2 CTAs/SM)
#define SMEM_W  (2 * STGW)                // wide: 110592 (1 CTA/SM)

// ---------------------------------------------------------------------------
__device__ __forceinline__ uint32_t smem_u32(const void* p) {
    uint32_t a;
    asm("{ .reg .u64 t; cvta.to.shared.u64 t, %1; cvt.u32.u64 %0, t; }" : "=r"(a) : "l"(p));
    return a;
}
#define CP_ASYNC16(dst, src) \
    asm volatile("cp.async.cg.shared.global [%0], [%1], 16;" :: "r"(dst), "l"(src) : "memory")
#define CP_COMMIT() asm volatile("cp.async.commit_group;" ::: "memory")
#define CP_WAIT0()  asm volatile("cp.async.wait_group 0;" ::: "memory")
#define CP_WAIT1()  asm volatile("cp.async.wait_group 1;" ::: "memory")

// ---------------------------------------------------------------------------
static __device__ __align__(16) __half g_qkp[4 * NBL * ND];
static __device__ __align__(16) __half g_vp[2 * NBL * ND];
static __device__ __align__(16) __half g_wqkp[4 * NHD * ND];
static __device__ __align__(16) __half g_wvp[2 * NHD * ND];
static __device__ __align__(16) __half g_fcwp[2 * ND * NHD];
static __device__ __align__(16) __half g_qkhp[2 * (size_t)NBL * NHD];
static __device__ __align__(16) __half g_vht[(size_t)NHD * NBL];
static __device__ __align__(16) __half g_hop[(size_t)NBL * NHD];
static __device__ __align__(16) __half g_ap[ATT];
static __device__ float g_tmp[(size_t)4 * NBL * ND];

// ---------------------------------------------------------------------------
__global__ void __launch_bounds__(256) cvt4_k(
    const float* __restrict__ s0, const float* __restrict__ s1,
    const float* __restrict__ s2, const float* __restrict__ s3,
    __half* __restrict__ d0, __half* __restrict__ d1,
    __half* __restrict__ d2, __half* __restrict__ d3,
    int n4)
{
    const int which = blockIdx.y;
    const float* x = which == 0 ? s0 : which == 1 ? s1 : which == 2 ? s2 : s3;
    __half* hi = which == 0 ? d0 : which == 1 ? d1 : which == 2 ? d2 : d3;
    int i = blockIdx.x * 256 + threadIdx.x;
    if (i >= n4) return;
    float4 v = *((const float4*)x + i);
    float f[4] = {v.x, v.y, v.z, v.w};
    __align__(8) __half h[4];
#pragma unroll
    for (int j = 0; j < 4; j++) h[j] = __float2half_rn(f[j]);
    *(uint2*)(hi + (size_t)i * 4) = *(uint2*)h;
}

// ---------------------------------------------------------------------------
// WIDE 1x1 GEMM: CTA tile 128x256, 8 warps of 64x64, BK=64, 2-stage cp.async.
// 16 MMAs per 8 LDSM per ks-step — high MMA density. 1 CTA/SM.
//   EPI 1: scores(scale/clip/mask->sentinel)  2: fp16 out
// ---------------------------------------------------------------------------
template <int EPI>
__global__ void __launch_bounds__(256, 1) tgemw(
    const __half* __restrict__ Ag, int lda,
    const __half* __restrict__ Bg, int ldb,
    void* __restrict__ Cgv, int ldc,
    int K, int nBdim,
    long sAb, long sAh, long sBb, long sBh, long sCb, long sCh,
    const int* __restrict__ maskg, long sMb)
{
    extern __shared__ __align__(16) char sm[];
    const uint32_t smb = smem_u32(sm);
    float* Cs = (float*)sm;

    const int tid = threadIdx.x;
    const int wid = tid >> 5;
    const int wm = wid & 1;   // 2 warp rows x 64
    const int wn = wid >> 1;  // 4 warp cols x 64

    const int z = blockIdx.z, zb = z % nBdim, zh = z / nBdim;
    const __half* Ap_ = Ag + (size_t)zb * sAb + (size_t)zh * sAh;
    const __half* Bp_ = Bg + (size_t)zb * sBb + (size_t)zh * sBh;

    const int rowBase = blockIdx.y * 128;
    const int colBase = blockIdx.x * 256;

    wmma::fragment<wmma::accumulator, 16, 16, 16, float> acc[4][4];
#pragma unroll
    for (int i = 0; i < 4; i++)
#pragma unroll
        for (int j = 0; j < 4; j++) wmma::fill_fragment(acc[i][j], 0.f);

    auto ldst = [&](int t, int s) {
        const int ko = t * BKK;
        const uint32_t sb = smb + s * STGW;
#pragma unroll
        for (int i = 0; i < 4; i++) {           // A: 128 rows
            const int c = tid + i * 256, row = c >> 3, col = (c & 7) * 8;
            const uint32_t soff = (uint32_t)(row * LDS_AB + col) * 2;
            CP_ASYNC16(sb + soff, Ap_ + (size_t)(rowBase + row) * lda + ko + col);
        }
#pragma unroll
        for (int i = 0; i < 8; i++) {           // B: 256 rows
            const int c = tid + i * 256, row = c >> 3, col = (c & 7) * 8;
            const uint32_t soff = (uint32_t)PLB + (uint32_t)(row * LDS_AB + col) * 2;
            CP_ASYNC16(sb + soff, Bp_ + (size_t)(colBase + row) * ldb + ko + col);
        }
        CP_COMMIT();
    };

    auto compute = [&](int s) {
        const __half* base = (const __half*)(sm + s * STGW);
        const __half* Ah0 = base + wm * 64 * LDS_AB;
        const __half* Bh0 = base + PLE + wn * 64 * LDS_AB;
#pragma unroll
        for (int ks = 0; ks < 4; ks++) {
            wmma::fragment<wmma::matrix_a, 16, 16, 16, __half, wmma::row_major> fah[4];
            wmma::fragment<wmma::matrix_b, 16, 16, 16, __half, wmma::col_major> fbh[4];
#pragma unroll
            for (int i = 0; i < 4; i++)
                wmma::load_matrix_sync(fah[i], Ah0 + i * 16 * LDS_AB + ks * 16, LDS_AB);
#pragma unroll
            for (int j = 0; j < 4; j++)
                wmma::load_matrix_sync(fbh[j], Bh0 + j * 16 * LDS_AB + ks * 16, LDS_AB);
#pragma unroll
            for (int i = 0; i < 4; i++)
#pragma unroll
                for (int j = 0; j < 4; j++)
                    wmma::mma_sync(acc[i][j], fah[i], fbh[j], acc[i][j]);
        }
    };

    const int T = K / BKK;
    ldst(0, 0);
    ldst(1, 1);
    for (int t = 0; t < T; t++) {
        if (t == T - 1) { CP_WAIT0(); } else { CP_WAIT1(); }
        __syncthreads();
        compute(t & 1);
        __syncthreads();
        if (t + 2 < T) ldst(t + 2, t & 1);
    }

    // ---- epilogue in two 128-col halves ----
    const int row = tid >> 1;
    const int ch  = (tid & 1) * 64;
#pragma unroll
    for (int half = 0; half < 2; half++) {
        __syncthreads();
        if ((wn >> 1) == half) {
#pragma unroll
            for (int i = 0; i < 4; i++)
#pragma unroll
                for (int j = 0; j < 4; j++)
                    wmma::store_matrix_sync(
                        Cs + (size_t)(wm * 64 + i * 16) * LDC_S + (wn & 1) * 64 + j * 16,
                        acc[i][j], LDC_S, wmma::mem_row_major);
        }
        __syncthreads();

        const float* crow = Cs + (size_t)row * LDC_S + ch;
        const int gr = rowBase + row;
        const int gc = colBase + half * 128 + ch;

        if (EPI == 2) {
            __half* Ch = (__half*)Cgv + (size_t)zb * sCb + (size_t)zh * sCh +
                         (size_t)gr * ldc + gc;
#pragma unroll
            for (int cb = 0; cb < 64; cb += 8) {
                __align__(16) __half hv[8];
#pragma unroll
                for (int j = 0; j < 8; j++) hv[j] = __float2half_rn(crow[cb + j]);
                *(uint4*)(Ch + cb) = *(uint4*)hv;
            }
        } else {  // EPI == 1: scores
            float* C = (float*)Cgv + (size_t)zb * sCb + (size_t)zh * sCh +
                       (size_t)gr * ldc + gc;
            const int* mrow = maskg + (size_t)zb * sMb + (size_t)gr * NL + gc;
#pragma unroll
            for (int j4 = 0; j4 < 16; j4++) {
                int4 m = *(const int4*)(mrow + j4 * 4);
                int mm[4] = {m.x, m.y, m.z, m.w};
                float ov[4];
#pragma unroll
                for (int j = 0; j < 4; j++) {
                    float s = crow[j4 * 4 + j] * 0.0625f;
                    s = fminf(15.f, fmaxf(-15.f, s));
                    ov[j] = mm[j] ? s : 30000.f;
                }
                *(float4*)(C + j4 * 4) = *(float4*)ov;
            }
        }
    }
}

// ---------------------------------------------------------------------------
// NARROW 1x1 GEMM (R15 geometry, occ 2) — kept for fc (N=128-col tiles).
// ---------------------------------------------------------------------------
template <int EPI>
__global__ void __launch_bounds__(256, 2) tgemm(
    const __half* __restrict__ Ag, int lda,
    const __half* __restrict__ Bg, int ldb,
    void* __restrict__ Cgv, int ldc,
    int K, int nBdim,
    long sAb, long sAh, long sBb, long sBh, long sCb, long sCh,
    const int* __restrict__ maskg, long sMb)
{
    constexpr int STGBT = 2 * PLB;
    extern __shared__ __align__(16) char sm[];
    const uint32_t smb = smem_u32(sm);
    float* Cs = (float*)sm;

    const int tid = threadIdx.x;
    const int wid = tid >> 5;
    const int wm = wid & 1;
    const int wn = wid >> 1;

    const int z = blockIdx.z, zb = z % nBdim, zh = z / nBdim;
    const __half* Ap_ = Ag + (size_t)zb * sAb + (size_t)zh * sAh;
    const __half* Bp_ = Bg + (size_t)zb * sBb + (size_t)zh * sBh;

    const int rowBase = blockIdx.y * 128;
    const int colBase = blockIdx.x * 128;

    wmma::fragment<wmma::accumulator, 16, 16, 16, float> acc[4][2];
#pragma unroll
    for (int i = 0; i < 4; i++)
#pragma unroll
        for (int j = 0; j < 2; j++) wmma::fill_fragment(acc[i][j], 0.f);

    auto ldst = [&](int t, int s) {
        const int ko = t * BKK;
        const uint32_t sb = smb + s * STGBT;
#pragma unroll
        for (int i = 0; i < 4; i++) {
            const int c = tid + i * 256;
            const int row = c >> 3, col = (c & 7) * 8;
            const uint32_t soff = (uint32_t)(row * LDS_AB + col) * 2;
            CP_ASYNC16(sb + soff, Ap_ + (size_t)(rowBase + row) * lda + ko + col);
            CP_ASYNC16(sb + PLB + soff, Bp_ + (size_t)(colBase + row) * ldb + ko + col);
        }
        CP_COMMIT();
    };

    auto compute = [&](int s) {
        const __half* base = (const __half*)(sm + s * STGBT);
        const __half* Ah0 = base + wm * 64 * LDS_AB;
        const __half* Bh0 = base + PLE + wn * 32 * LDS_AB;
#pragma unroll
        for (int ks = 0; ks < 4; ks++) {
            wmma::fragment<wmma::matrix_a, 16, 16, 16, __half, wmma::row_major> fah[4];
            wmma::fragment<wmma::matrix_b, 16, 16, 16, __half, wmma::col_major> fbh[2];
#pragma unroll
            for (int i = 0; i < 4; i++)
                wmma::load_matrix_sync(fah[i], Ah0 + i * 16 * LDS_AB + ks * 16, LDS_AB);
#pragma unroll
            for (int j = 0; j < 2; j++)
                wmma::load_matrix_sync(fbh[j], Bh0 + j * 16 * LDS_AB + ks * 16, LDS_AB);
#pragma unroll
            for (int i = 0; i < 4; i++)
#pragma unroll
                for (int j = 0; j < 2; j++)
                    wmma::mma_sync(acc[i][j], fah[i], fbh[j], acc[i][j]);
        }
    };

    const int T = K / BKK;
    ldst(0, 0);
    ldst(1, 1);
    for (int t = 0; t < T; t++) {
        if (t == T - 1) { CP_WAIT0(); } else { CP_WAIT1(); }
        __syncthreads();
        compute(t & 1);
        __syncthreads();
        if (t + 2 < T) ldst(t + 2, t & 1);
    }

#pragma unroll
    for (int i = 0; i < 4; i++)
#pragma unroll
        for (int j = 0; j < 2; j++)
            wmma::store_matrix_sync(Cs + (size_t)(wm * 64 + i * 16) * LDC_S + wn * 32 + j * 16,
                                    acc[i][j], LDC_S, wmma::mem_row_major);
    __syncthreads();

    const int row = tid >> 1;
    const int ch  = (tid & 1) * 64;
    const float* crow = Cs + (size_t)row * LDC_S + ch;
    const int gr = rowBase + row;
    const int gc = colBase + ch;

    {   // EPI == 3: plain fp32 (only instantiation used)
        float* C = (float*)Cgv + (size_t)zb * sCb + (size_t)zh * sCh + (size_t)gr * ldc + gc;
#pragma unroll
        for (int j4 = 0; j4 < 16; j4++) {
            float ov[4] = {crow[j4 * 4], crow[j4 * 4 + 1], crow[j4 * 4 + 2], crow[j4 * 4 + 3]};
            *(float4*)(C + j4 * 4) = *(float4*)ov;
        }
    }
    (void)maskg; (void)sMb;
}

// ---------------------------------------------------------------------------
__global__ void __launch_bounds__(256) softmax_k(float* __restrict__ attn,
                                                 __half* __restrict__ ap)
{
    __shared__ float sh[8];
    const size_t rbase = (size_t)blockIdx.x * 1024;
    float* p = attn + rbase;
    const int t = threadIdx.x;

    float4 v4 = ((const float4*)p)[t];
    float x[4] = {v4.x, v4.y, v4.z, v4.w};
    bool msk[4];
    float mx = -1e30f;
#pragma unroll
    for (int i = 0; i < 4; i++) {
        msk[i] = (x[i] > 1000.f);
        if (msk[i]) x[i] = 0.f;
        mx = fmaxf(mx, x[i]);
    }
#pragma unroll
    for (int o = 16; o; o >>= 1) mx = fmaxf(mx, __shfl_xor_sync(0xffffffffu, mx, o));
    if ((t & 31) == 0) sh[t >> 5] = mx;
    __syncthreads();
    mx = sh[0];
#pragma unroll
    for (int i = 1; i < 8; i++) mx = fmaxf(mx, sh[i]);

    float e[4], s = 0.f;
#pragma unroll
    for (int i = 0; i < 4; i++) {
        e[i] = msk[i] ? 0.f : __expf(x[i] - mx);
        s += e[i];
    }
#pragma unroll
    for (int o = 16; o; o >>= 1) s += __shfl_xor_sync(0xffffffffu, s, o);
    __syncthreads();
    if ((t & 31) == 0) sh[t >> 5] = s;
    __syncthreads();
    s = 0.f;
#pragma unroll
    for (int i = 0; i < 8; i++) s += sh[i];

    const float inv = 1.f / (s + 1e-6f);
    float ov[4] = {e[0] * inv, e[1] * inv, e[2] * inv, e[3] * inv};
    ((float4*)p)[t] = *(float4*)ov;

    __align__(8) __half h[4];
#pragma unroll
    for (int i = 0; i < 4; i++) h[i] = __float2half_rn(ov[i]);
    *(uint2*)(ap + rbase + (size_t)t * 4) = *(uint2*)h;
}

// ---------------------------------------------------------------------------
__global__ void __launch_bounds__(256) fc_ln_k(
    const float* __restrict__ tmp, const float* __restrict__ fcb,
    const float* __restrict__ resid, const float* __restrict__ lg,
    const float* __restrict__ lb, float* __restrict__ out)
{
    __shared__ float shs[8], shq[8];
    const size_t o = (size_t)blockIdx.x * 256 + threadIdx.x;
    const int t = threadIdx.x;

    float v = tmp[o] + tmp[o + 1048576] + tmp[o + 2097152] + tmp[o + 3145728]
            + fcb[t] + resid[o];

    float s = v, qq = v * v;
#pragma unroll
    for (int d = 16; d; d >>= 1) {
        s  += __shfl_xor_sync(0xffffffffu, s, d);
        qq += __shfl_xor_sync(0xffffffffu, qq, d);
    }
    if ((t & 31) == 0) { shs[t >> 5] = s; shq[t >> 5] = qq; }
    __syncthreads();
    s = 0.f; qq = 0.f;
#pragma unroll
    for (int i = 0; i < 8; i++) { s += shs[i]; qq += shq[i]; }

    const float mean = s * (1.f / 256.f);
    const float var  = qq * (1.f / 256.f) - mean * mean;
    out[o] = (v - mean) * rsqrtf(var + 1e-5f) * lg[t] + lb[t];
}

// ---------------------------------------------------------------------------
extern "C" void kernel_launch(void* const* d_in, const int* in_sizes, int n_in,
                              void* d_out, int out_size)
{
    const float* q    = (const float*)d_in[0];
    const int*   mask = (const int*)  d_in[1];
    const float* k    = (const float*)d_in[2];
    const float* v    = (const float*)d_in[3];
    const float* w_qs = (const float*)d_in[4];
    const float* w_ks = (const float*)d_in[5];
    const float* w_vs = (const float*)d_in[6];
    const float* fc_w = (const float*)d_in[7];
    const float* fc_b = (const float*)d_in[8];
    const float* ln_g = (const float*)d_in[9];
    const float* ln_b = (const float*)d_in[10];

    float* out  = (float*)d_out;
    float* attn = out + (size_t)NBL * ND;

    __half *qkp, *vp, *wqkp, *wvp, *fcwp, *qkhp, *vht, *hop, *ap;
    float* tmp;
    cudaGetSymbolAddress((void**)&qkp,  g_qkp);
    cudaGetSymbolAddress((void**)&vp,   g_vp);
    cudaGetSymbolAddress((void**)&wqkp, g_wqkp);
    cudaGetSymbolAddress((void**)&wvp,  g_wvp);
    cudaGetSymbolAddress((void**)&fcwp, g_fcwp);
    cudaGetSymbolAddress((void**)&qkhp, g_qkhp);
    cudaGetSymbolAddress((void**)&vht,  g_vht);
    cudaGetSymbolAddress((void**)&hop,  g_hop);
    cudaGetSymbolAddress((void**)&ap,   g_ap);
    cudaGetSymbolAddress((void**)&tmp,  g_tmp);

    cudaFuncSetAttribute(tgemw<1>, cudaFuncAttributeMaxDynamicSharedMemorySize, SMEM_W);
    cudaFuncSetAttribute(tgemw<2>, cudaFuncAttributeMaxDynamicSharedMemorySize, SMEM_W);
    cudaFuncSetAttribute(tgemm<3>, cudaFuncAttributeMaxDynamicSharedMemorySize, SMEM_11);

    static cudaStream_t s1 = [] {
        cudaStream_t s; cudaStreamCreateWithFlags(&s, cudaStreamNonBlocking); return s;
    }();
    static cudaEvent_t e0 = [] {
        cudaEvent_t e; cudaEventCreateWithFlags(&e, cudaEventDisableTiming); return e;
    }();
    static cudaEvent_t e_qkv = [] {
        cudaEvent_t e; cudaEventCreateWithFlags(&e, cudaEventDisableTiming); return e;
    }();
    static cudaEvent_t e_w = [] {
        cudaEvent_t e; cudaEventCreateWithFlags(&e, cudaEventDisableTiming); return e;
    }();
    static cudaEvent_t e_pv = [] {
        cudaEvent_t e; cudaEventCreateWithFlags(&e, cudaEventDisableTiming); return e;
    }();

    const long QKSZ = (long)NBL * ND;
    const long WSZ  = (long)NHD * ND;
    const long BIG  = (long)NBL * NHD;

    // ---- fork side stream ----
    cudaEventRecord(e0, 0);
    cudaStreamWaitEvent(s1, e0, 0);

    // s0: convert q/k/v (k at qkp + 2*QKSZ)
    cvt4_k<<<dim3(NBL * ND / 4 / 256, 3), 256>>>(
        q, k, v, v, qkp, qkp + 2 * QKSZ, vp, vp, NBL * ND / 4);
    cudaEventRecord(e_qkv, 0);

    // s1: convert weights (wk at wqkp + 2*WSZ)
    cvt4_k<<<dim3(NHD * ND / 4 / 256, 4), 256, 0, s1>>>(
        w_qs, w_ks, w_vs, fc_w, wqkp, wqkp + 2 * WSZ, wvp, fcwp, NHD * ND / 4);
    cudaEventRecord(e_w, s1);

    // s1: V projection (wide): vht[hd, token] = w_vs @ v^T, N=4096
    cudaStreamWaitEvent(s1, e_qkv, 0);
    tgemw<2><<<dim3(16, 16, 1), 256, SMEM_W, s1>>>(
        wvp, ND, vp, ND, vht, NBL, ND, 1,
        0, 0, 0, 0, 0, 0, nullptr, 0);
    cudaEventRecord(e_pv, s1);

    // s0: Q+K projections fused (wide), z selects q/k, N=2048
    cudaStreamWaitEvent(0, e_w, 0);
    tgemw<2><<<dim3(8, 32, 2), 256, SMEM_W>>>(
        qkp, ND, wqkp, ND, qkhp, NHD, ND, 1,
        0, 2 * QKSZ,
        0, 2 * WSZ,
        0, BIG,
        nullptr, 0);

    // s0: scores (wide): attn = qh @ kh^T /16, clip, mask; N=1024
    tgemw<1><<<dim3(4, 8, 32), 256, SMEM_W>>>(
        qkhp, NHD, qkhp + BIG, NHD, attn, NL, ND, NB,
        (long)NL * NHD, (long)ND,
        (long)NL * NHD, (long)ND,
        (long)NL * NL, (long)NB * NL * NL,
        mask, (long)NL * NL);

    // s0: masked softmax in place + fp16 plane
    softmax_k<<<NH * NB * NL, 256>>>(attn, ap);

    // s0: attn @ V (wide, join with projV); N=256 -> grid.x=1
    cudaStreamWaitEvent(0, e_pv, 0);
    tgemw<2><<<dim3(1, 8, 32), 256, SMEM_W>>>(
        ap, NL, vht, NBL, hop, NHD, NL, NB,
        (long)NL * NL, (long)NB * NL * NL,
        (long)NL, (long)ND * NBL,
        (long)NL * NHD, (long)ND,
        nullptr, 0);

    // s0: fc (narrow, occ 2): split-K = 4 -> fp32 partials
    tgemm<3><<<dim3(2, 32, 4), 256, SMEM_11>>>(
        hop, NHD, fcwp, NHD, tmp, ND, 512, 1,
        0, 512, 0, 512, 0, (long)NBL * ND, nullptr, 0);

    // s0: reduce + bias + residual + LayerNorm
    fc_ln_k<<<NBL, 256>>>(tmp, fc_b, q, ln_g, ln_b, out);
}

// round 17
// speedup vs baseline: 1.0147x; 1.0147x over previous
#include <cuda_runtime.h>
#include <cuda_fp16.h>
#include <mma.h>
#include <cstdint>

using namespace nvcuda;

#define NB 4
#define NL 1024
#define ND 256
#define NH 8
#define NHD 2048
#define NBL 4096
#define ATT ((size_t)NB * NH * NL * NL)

#define BKK 64
#define LDS_AB 72              // BK(64) + 8 pad -> 144B rows, LDSM conflict-free
#define PLE (128 * LDS_AB)
#define PLB (PLE * 2)
#define LDC_S 132
#define SMEM_11 (2 * 2 * PLB)  // 73728 B (2 CTAs/SM)

// ---------------------------------------------------------------------------
__device__ __forceinline__ uint32_t smem_u32(const void* p) {
    uint32_t a;
    asm("{ .reg .u64 t; cvta.to.shared.u64 t, %1; cvt.u32.u64 %0, t; }" : "=r"(a) : "l"(p));
    return a;
}
#define CP_ASYNC16(dst, src) \
    asm volatile("cp.async.cg.shared.global [%0], [%1], 16;" :: "r"(dst), "l"(src) : "memory")
#define CP_COMMIT() asm volatile("cp.async.commit_group;" ::: "memory")
#define CP_WAIT0()  asm volatile("cp.async.wait_group 0;" ::: "memory")
#define CP_WAIT1()  asm volatile("cp.async.wait_group 1;" ::: "memory")

// ---------------------------------------------------------------------------
// scratch (device globals — allocations forbidden)
// ---------------------------------------------------------------------------
static __device__ __align__(16) __half g_qkvp[3 * NBL * ND];          // q|k|v fp16
static __device__ __align__(16) __half g_wqkvp[3 * NHD * ND];         // wq|wk|wv
static __device__ __align__(16) __half g_fcwp[(size_t)ND * NHD];
static __device__ __align__(16) __half g_qkvhp[3 * (size_t)NBL * NHD]; // qh|kh|vh
static __device__ __align__(16) __half g_ap[ATT];                      // softmax fp16
static __device__ __align__(16) __half g_gt[(size_t)32 * 256 * 1024];  // Gt[b,h]
static __device__ float g_tmp[(size_t)4 * NBL * ND];                   // split-K partials

// ---------------------------------------------------------------------------
__global__ void __launch_bounds__(256) cvt4_k(
    const float* __restrict__ s0, const float* __restrict__ s1,
    const float* __restrict__ s2, const float* __restrict__ s3,
    __half* __restrict__ d0, __half* __restrict__ d1,
    __half* __restrict__ d2, __half* __restrict__ d3,
    int n4)
{
    const int which = blockIdx.y;
    const float* x = which == 0 ? s0 : which == 1 ? s1 : which == 2 ? s2 : s3;
    __half* hi = which == 0 ? d0 : which == 1 ? d1 : which == 2 ? d2 : d3;
    int i = blockIdx.x * 256 + threadIdx.x;
    if (i >= n4) return;
    float4 v = *((const float4*)x + i);
    float f[4] = {v.x, v.y, v.z, v.w};
    __align__(8) __half h[4];
#pragma unroll
    for (int j = 0; j < 4; j++) h[j] = __float2half_rn(f[j]);
    *(uint2*)(hi + (size_t)i * 4) = *(uint2*)h;
}

// ---------------------------------------------------------------------------
// Narrow fp16 1x1 GEMM (R15 geometry: 64x32 warp tiles, occ 2) with optional
// block-strided K addressing:
//   kg = zh*KZH + t*BKK;  operand base += (kg>>HS)*sK?;  in-block k = kg & mask.
// Standard launches pass sKA=sKB=KZH=0, HS=30.
//   EPI 1: scores(scale/clip/mask->sentinel)  2: fp16 out  3: fp32 out
// ---------------------------------------------------------------------------
template <int EPI>
__global__ void __launch_bounds__(256, 2) tgemm(
    const __half* __restrict__ Ag, int lda,
    const __half* __restrict__ Bg, int ldb,
    void* __restrict__ Cgv, int ldc,
    int K, int nBdim,
    long sAb, long sAh, long sBb, long sBh, long sCb, long sCh,
    long sKA, long sKB, int HS, int KZH,
    const int* __restrict__ maskg, long sMb)
{
    constexpr int STGBT = 2 * PLB;
    extern __shared__ __align__(16) char sm[];
    const uint32_t smb = smem_u32(sm);
    float* Cs = (float*)sm;

    const int tid = threadIdx.x;
    const int wid = tid >> 5;
    const int wm = wid & 1;
    const int wn = wid >> 1;

    const int z = blockIdx.z, zb = z % nBdim, zh = z / nBdim;
    const __half* Ap_ = Ag + (size_t)zb * sAb + (size_t)zh * sAh;
    const __half* Bp_ = Bg + (size_t)zb * sBb + (size_t)zh * sBh;

    const int rowBase = blockIdx.y * 128;
    const int colBase = blockIdx.x * 128;

    wmma::fragment<wmma::accumulator, 16, 16, 16, float> acc[4][2];
#pragma unroll
    for (int i = 0; i < 4; i++)
#pragma unroll
        for (int j = 0; j < 2; j++) wmma::fill_fragment(acc[i][j], 0.f);

    auto ldst = [&](int t, int s) {
        const long kg = (long)zh * KZH + (long)t * BKK;
        const long kblk = kg >> HS;
        const int  kin  = (int)(kg & ((1L << HS) - 1));
        const __half* Ab = Ap_ + kblk * sKA + kin;
        const __half* Bb = Bp_ + kblk * sKB + kin;
        const uint32_t sb = smb + s * STGBT;
#pragma unroll
        for (int i = 0; i < 4; i++) {
            const int c = tid + i * 256;
            const int row = c >> 3, col = (c & 7) * 8;
            const uint32_t soff = (uint32_t)(row * LDS_AB + col) * 2;
            CP_ASYNC16(sb + soff,       Ab + (size_t)(rowBase + row) * lda + col);
            CP_ASYNC16(sb + PLB + soff, Bb + (size_t)(colBase + row) * ldb + col);
        }
        CP_COMMIT();
    };

    auto compute = [&](int s) {
        const __half* base = (const __half*)(sm + s * STGBT);
        const __half* Ah0 = base + wm * 64 * LDS_AB;
        const __half* Bh0 = base + PLE + wn * 32 * LDS_AB;
#pragma unroll
        for (int ks = 0; ks < 4; ks++) {
            wmma::fragment<wmma::matrix_a, 16, 16, 16, __half, wmma::row_major> fah[4];
            wmma::fragment<wmma::matrix_b, 16, 16, 16, __half, wmma::col_major> fbh[2];
#pragma unroll
            for (int i = 0; i < 4; i++)
                wmma::load_matrix_sync(fah[i], Ah0 + i * 16 * LDS_AB + ks * 16, LDS_AB);
#pragma unroll
            for (int j = 0; j < 2; j++)
                wmma::load_matrix_sync(fbh[j], Bh0 + j * 16 * LDS_AB + ks * 16, LDS_AB);
#pragma unroll
            for (int i = 0; i < 4; i++)
#pragma unroll
                for (int j = 0; j < 2; j++)
                    wmma::mma_sync(acc[i][j], fah[i], fbh[j], acc[i][j]);
        }
    };

    const int T = K / BKK;
    ldst(0, 0);
    ldst(1, 1);
    for (int t = 0; t < T; t++) {
        if (t == T - 1) { CP_WAIT0(); } else { CP_WAIT1(); }
        __syncthreads();
        compute(t & 1);
        __syncthreads();
        if (t + 2 < T) ldst(t + 2, t & 1);
    }

#pragma unroll
    for (int i = 0; i < 4; i++)
#pragma unroll
        for (int j = 0; j < 2; j++)
            wmma::store_matrix_sync(Cs + (size_t)(wm * 64 + i * 16) * LDC_S + wn * 32 + j * 16,
                                    acc[i][j], LDC_S, wmma::mem_row_major);
    __syncthreads();

    const int row = tid >> 1;
    const int ch  = (tid & 1) * 64;
    const float* crow = Cs + (size_t)row * LDC_S + ch;
    const int gr = rowBase + row;
    const int gc = colBase + ch;

    if (EPI == 2) {
        __half* Ch = (__half*)Cgv + (size_t)zb * sCb + (size_t)zh * sCh +
                     (size_t)gr * ldc + gc;
#pragma unroll
        for (int cb = 0; cb < 64; cb += 8) {
            __align__(16) __half hv[8];
#pragma unroll
            for (int j = 0; j < 8; j++) hv[j] = __float2half_rn(crow[cb + j]);
            *(uint4*)(Ch + cb) = *(uint4*)hv;
        }
    } else if (EPI == 1) {
        float* C = (float*)Cgv + (size_t)zb * sCb + (size_t)zh * sCh + (size_t)gr * ldc + gc;
        const int* mrow = maskg + (size_t)zb * sMb + (size_t)gr * NL + gc;
#pragma unroll
        for (int j4 = 0; j4 < 16; j4++) {
            int4 m = *(const int4*)(mrow + j4 * 4);
            int mm[4] = {m.x, m.y, m.z, m.w};
            float ov[4];
#pragma unroll
            for (int j = 0; j < 4; j++) {
                float s = crow[j4 * 4 + j] * 0.0625f;   // 1/sqrt(256)
                s = fminf(15.f, fmaxf(-15.f, s));
                ov[j] = mm[j] ? s : 30000.f;
            }
            *(float4*)(C + j4 * 4) = *(float4*)ov;
        }
    } else {  // EPI == 3: plain fp32
        float* C = (float*)Cgv + (size_t)zb * sCb + (size_t)zh * sCh + (size_t)gr * ldc + gc;
#pragma unroll
        for (int j4 = 0; j4 < 16; j4++) {
            float ov[4] = {crow[j4 * 4], crow[j4 * 4 + 1], crow[j4 * 4 + 2], crow[j4 * 4 + 3]};
            *(float4*)(C + j4 * 4) = *(float4*)ov;
        }
    }
}

// ---------------------------------------------------------------------------
__global__ void __launch_bounds__(256) softmax_k(float* __restrict__ attn,
                                                 __half* __restrict__ ap)
{
    __shared__ float sh[8];
    const size_t rbase = (size_t)blockIdx.x * 1024;
    float* p = attn + rbase;
    const int t = threadIdx.x;

    float4 v4 = ((const float4*)p)[t];
    float x[4] = {v4.x, v4.y, v4.z, v4.w};
    bool msk[4];
    float mx = -1e30f;
#pragma unroll
    for (int i = 0; i < 4; i++) {
        msk[i] = (x[i] > 1000.f);
        if (msk[i]) x[i] = 0.f;
        mx = fmaxf(mx, x[i]);
    }
#pragma unroll
    for (int o = 16; o; o >>= 1) mx = fmaxf(mx, __shfl_xor_sync(0xffffffffu, mx, o));
    if ((t & 31) == 0) sh[t >> 5] = mx;
    __syncthreads();
    mx = sh[0];
#pragma unroll
    for (int i = 1; i < 8; i++) mx = fmaxf(mx, sh[i]);

    float e[4], s = 0.f;
#pragma unroll
    for (int i = 0; i < 4; i++) {
        e[i] = msk[i] ? 0.f : __expf(x[i] - mx);
        s += e[i];
    }
#pragma unroll
    for (int o = 16; o; o >>= 1) s += __shfl_xor_sync(0xffffffffu, s, o);
    __syncthreads();
    if ((t & 31) == 0) sh[t >> 5] = s;
    __syncthreads();
    s = 0.f;
#pragma unroll
    for (int i = 0; i < 8; i++) s += sh[i];

    const float inv = 1.f / (s + 1e-6f);
    float ov[4] = {e[0] * inv, e[1] * inv, e[2] * inv, e[3] * inv};
    ((float4*)p)[t] = *(float4*)ov;

    __align__(8) __half h[4];
#pragma unroll
    for (int i = 0; i < 4; i++) h[i] = __float2half_rn(ov[i]);
    *(uint2*)(ap + rbase + (size_t)t * 4) = *(uint2*)h;
}

// ---------------------------------------------------------------------------
__global__ void __launch_bounds__(256) fc_ln_k(
    const float* __restrict__ tmp, const float* __restrict__ fcb,
    const float* __restrict__ resid, const float* __restrict__ lg,
    const float* __restrict__ lb, float* __restrict__ out)
{
    __shared__ float shs[8], shq[8];
    const size_t o = (size_t)blockIdx.x * 256 + threadIdx.x;
    const int t = threadIdx.x;

    float v = tmp[o] + tmp[o + 1048576] + tmp[o + 2097152] + tmp[o + 3145728]
            + fcb[t] + resid[o];

    float s = v, qq = v * v;
#pragma unroll
    for (int d = 16; d; d >>= 1) {
        s  += __shfl_xor_sync(0xffffffffu, s, d);
        qq += __shfl_xor_sync(0xffffffffu, qq, d);
    }
    if ((t & 31) == 0) { shs[t >> 5] = s; shq[t >> 5] = qq; }
    __syncthreads();
    s = 0.f; qq = 0.f;
#pragma unroll
    for (int i = 0; i < 8; i++) { s += shs[i]; qq += shq[i]; }

    const float mean = s * (1.f / 256.f);
    const float var  = qq * (1.f / 256.f) - mean * mean;
    out[o] = (v - mean) * rsqrtf(var + 1e-5f) * lg[t] + lb[t];
}

// ---------------------------------------------------------------------------
extern "C" void kernel_launch(void* const* d_in, const int* in_sizes, int n_in,
                              void* d_out, int out_size)
{
    const float* q    = (const float*)d_in[0];
    const int*   mask = (const int*)  d_in[1];
    const float* k    = (const float*)d_in[2];
    const float* v    = (const float*)d_in[3];
    const float* w_qs = (const float*)d_in[4];
    const float* w_ks = (const float*)d_in[5];
    const float* w_vs = (const float*)d_in[6];
    const float* fc_w = (const float*)d_in[7];
    const float* fc_b = (const float*)d_in[8];
    const float* ln_g = (const float*)d_in[9];
    const float* ln_b = (const float*)d_in[10];

    float* out  = (float*)d_out;
    float* attn = out + (size_t)NBL * ND;

    __half *qkvp, *wqkvp, *fcwp, *qkvhp, *ap, *gt;
    float* tmp;
    cudaGetSymbolAddress((void**)&qkvp,  g_qkvp);
    cudaGetSymbolAddress((void**)&wqkvp, g_wqkvp);
    cudaGetSymbolAddress((void**)&fcwp,  g_fcwp);
    cudaGetSymbolAddress((void**)&qkvhp, g_qkvhp);
    cudaGetSymbolAddress((void**)&ap,    g_ap);
    cudaGetSymbolAddress((void**)&gt,    g_gt);
    cudaGetSymbolAddress((void**)&tmp,   g_tmp);

    cudaFuncSetAttribute(tgemm<1>, cudaFuncAttributeMaxDynamicSharedMemorySize, SMEM_11);
    cudaFuncSetAttribute(tgemm<2>, cudaFuncAttributeMaxDynamicSharedMemorySize, SMEM_11);
    cudaFuncSetAttribute(tgemm<3>, cudaFuncAttributeMaxDynamicSharedMemorySize, SMEM_11);

    static cudaStream_t s1 = [] {
        cudaStream_t s; cudaStreamCreateWithFlags(&s, cudaStreamNonBlocking); return s;
    }();
    static cudaEvent_t e0 = [] {
        cudaEvent_t e; cudaEventCreateWithFlags(&e, cudaEventDisableTiming); return e;
    }();
    static cudaEvent_t e_w = [] {
        cudaEvent_t e; cudaEventCreateWithFlags(&e, cudaEventDisableTiming); return e;
    }();
    static cudaEvent_t e_pq = [] {
        cudaEvent_t e; cudaEventCreateWithFlags(&e, cudaEventDisableTiming); return e;
    }();
    static cudaEvent_t e_gt = [] {
        cudaEvent_t e; cudaEventCreateWithFlags(&e, cudaEventDisableTiming); return e;
    }();

    const long QKSZ = (long)NBL * ND;        // 1048576
    const long WSZ  = (long)NHD * ND;        // 524288
    const long BIG  = (long)NBL * NHD;       // 8388608

    // ---- fork side stream ----
    cudaEventRecord(e0, 0);
    cudaStreamWaitEvent(s1, e0, 0);

    // s0: convert q/k/v -> qkvp (strides QKSZ)
    cvt4_k<<<dim3(NBL * ND / 4 / 256, 3), 256>>>(
        q, k, v, v, qkvp, qkvp + QKSZ, qkvp + 2 * QKSZ, qkvp, NBL * ND / 4);

    // s1: convert wq/wk/wv/fcw
    cvt4_k<<<dim3(NHD * ND / 4 / 256, 4), 256, 0, s1>>>(
        w_qs, w_ks, w_vs, fc_w, wqkvp, wqkvp + WSZ, wqkvp + 2 * WSZ, fcwp, NHD * ND / 4);
    cudaEventRecord(e_w, s1);

    // s0: fused Q/K/V projections, z selects which (needs both cvts)
    cudaStreamWaitEvent(0, e_w, 0);
    tgemm<2><<<dim3(16, 32, 3), 256, SMEM_11>>>(
        qkvp, ND, wqkvp, ND, qkvhp, NHD, ND, 1,
        0, QKSZ, 0, WSZ, 0, BIG,
        0, 0, 30, 0, nullptr, 0);
    cudaEventRecord(e_pq, 0);

    // s1: Gt[b,h] = F_h @ V_{b,h}^T  (overlaps with scores/softmax on s0)
    cudaStreamWaitEvent(s1, e_pq, 0);
    tgemm<2><<<dim3(8, 2, 32), 256, SMEM_11, s1>>>(
        fcwp, NHD, qkvhp + 2 * BIG, NHD, gt, NL, ND, NB,
        0, (long)ND,                        // A: fcw, head k-offset
        (long)NL * NHD, (long)ND,           // B: vh tokens per batch, head offset
        (long)ND * NL, (long)NB * ND * NL,  // C: gt[(zh*4+zb)]
        0, 0, 30, 0, nullptr, 0);
    cudaEventRecord(e_gt, s1);

    // s0: scores: attn[(h*B+b)] = qh @ kh^T /16, clip, mask
    tgemm<1><<<dim3(8, 8, 32), 256, SMEM_11>>>(
        qkvhp, NHD, qkvhp + BIG, NHD, attn, NL, ND, NB,
        (long)NL * NHD, (long)ND,
        (long)NL * NHD, (long)ND,
        (long)NL * NL, (long)NB * NL * NL,
        0, 0, 30, 0, mask, (long)NL * NL);

    // s0: masked softmax in place + fp16 plane
    softmax_k<<<NH * NB * NL, 256>>>(attn, ap);

    // s0: fused attn@V + fc: out_pre = sum_h A_h @ Gt_h^T, block-K=1024,
    //     K=2048 per split (2 heads), 4 splits -> tmp partials
    cudaStreamWaitEvent(0, e_gt, 0);
    tgemm<3><<<dim3(2, 8, 16), 256, SMEM_11>>>(
        ap, NL, gt, NL, tmp, ND, 2048, NB,
        (long)NL * NL, 0,                    // A: batch offset; h via sKA
        (long)ND * NL, 0,                    // B: batch offset; h via sKB
        (long)NL * ND, (long)NBL * ND,       // C: zb token block, zh split
        (long)NB * NL * NL,                  // sKA: h stride in ap
        (long)NB * ND * NL,                  // sKB: h stride in gt
        10, 2048,                            // HS (1024 block), KZH (split k-base)
        nullptr, 0);

    // s0: reduce partials + bias + residual + LayerNorm
    fc_ln_k<<<NBL, 256>>>(tmp, fc_b, q, ln_g, ln_b, out);
}